// round 8
// baseline (speedup 1.0000x reference)
#include <cuda_runtime.h>
#include <cuda_bf16.h>
#include <stdint.h>
#include <math.h>

#define N_NODES 50000
#define N_EDGES 800000
#define F_IN    128
#define HID     256
#define N_OUT   10
#define N_G     128
#define T_STEPS 15
#define TILE    128
#define N_TILES 391   // ceil(50000/128)

#define RNG_TOTAL   (T_STEPS * N_NODES * 4)          // 3,000,000
#define RNG1_BLOCKS 7000
#define RNG1_END    (RNG1_BLOCKS * 256)              // 1,792,000
#define RNG2_BLOCKS ((RNG_TOTAL - RNG1_END + 255) / 256)   // 4719
#define CNT_BLOCKS  ((N_EDGES + 255) / 256)          // 3125
#define FILL_BLOCKS ((N_EDGES + 255) / 256)          // 3125
#define PREP_BLOCKS ((N_NODES + 255) / 256)          // 196
#define W1P_BLOCKS  32
#define SCAN_TPB    1024
#define SCAN_NB     ((N_NODES + SCAN_TPB - 1) / SCAN_TPB)  // 49

// ---------------- device scratch ----------------
__device__ uint4  d_xtbits4[(size_t)T_STEPS * N_NODES];  // 12 MB bitpacked x_t
__device__ uint4  d_W1q[8192];                           // 128KB packed bf16 hi/lo fragments
__device__ int    d_degcnt[N_NODES];
__device__ int    d_rowptr[N_NODES + 1];
__device__ int    d_cursor[N_NODES];
__device__ int    d_colsrc[N_EDGES];
__device__ int    d_bsum[SCAN_NB];
__device__ float  d_invdeg[N_NODES];
__device__ float  d_invsqrt[N_NODES];
__device__ int    d_gcnt[N_G];
__device__ float  d_invcnt[N_G];
__device__ float  d_M[HID * N_OUT];
__device__ float  d_y[(size_t)N_NODES * N_OUT];
__device__ float  d_P[N_G * N_OUT];

struct Keys { unsigned k0[T_STEPS]; unsigned k1[T_STEPS]; };

// ---------------- host threefry for subkeys ----------------
static void threefry_pair_host(uint32_t k0, uint32_t k1, uint32_t x0, uint32_t x1,
                               uint32_t* o0, uint32_t* o1) {
    uint32_t ks2 = k0 ^ k1 ^ 0x1BD11BDAu;
    x0 += k0; x1 += k1;
#define HR(R) { x0 += x1; x1 = (x1 << R) | (x1 >> (32 - R)); x1 ^= x0; }
    HR(13) HR(15) HR(26) HR(6)
    x0 += k1; x1 += ks2 + 1u;
    HR(17) HR(29) HR(16) HR(24)
    x0 += ks2; x1 += k0 + 2u;
    HR(13) HR(15) HR(26) HR(6)
    x0 += k0; x1 += k1 + 3u;
    HR(17) HR(29) HR(16) HR(24)
    x0 += k1; x1 += ks2 + 4u;
    HR(13) HR(15) HR(26) HR(6)
    x0 += ks2; x1 += k0 + 5u;
#undef HR
    *o0 = x0; *o1 = x1;
}

// ---------------- device RNG body: JAX threefry2x32 partitionable ----------------
#define DR(R) { x0 += x1; x1 = __funnelshift_l(x1, x1, R); x1 ^= x0; }

__device__ __forceinline__ void rng_body(int gid, const float* __restrict__ x, const Keys& keys) {
    if (gid >= RNG_TOTAL) return;
    int w  = gid & 3;
    int nw = gid >> 2;
    int n  = nw % N_NODES;
    int t  = nw / N_NODES;
    const unsigned k0 = keys.k0[t];
    const unsigned k1 = keys.k1[t];
    const unsigned ks2 = k0 ^ k1 ^ 0x1BD11BDAu;
    const unsigned base = (unsigned)(n * F_IN + w * 32);
    const float* xr = x + n * F_IN + w * 32;
    unsigned outw = 0u;
    #pragma unroll 4
    for (int b = 0; b < 32; b++) {
        unsigned x0 = k0;
        unsigned x1 = base + (unsigned)b + k1;
        DR(13) DR(15) DR(26) DR(6)
        x0 += k1;  x1 += ks2 + 1u;
        DR(17) DR(29) DR(16) DR(24)
        x0 += ks2; x1 += k0 + 2u;
        DR(13) DR(15) DR(26) DR(6)
        x0 += k0;  x1 += k1 + 3u;
        DR(17) DR(29) DR(16) DR(24)
        x0 += k1;  x1 += ks2 + 4u;
        DR(13) DR(15) DR(26) DR(6)
        x0 += ks2; x1 += k0 + 5u;
        unsigned bits = x0 ^ x1;
        float u = __uint_as_float((bits >> 9) | 0x3f800000u) - 1.0f;
        if (u < xr[b]) outw |= (1u << b);
    }
    ((unsigned*)d_xtbits4)[gid] = outw;
}
#undef DR

// ---------------- prep bodies ----------------
__global__ void init_kernel() {
    int i = blockIdx.x * blockDim.x + threadIdx.x;
    if (i < N_NODES) { d_degcnt[i] = 0; d_cursor[i] = 0; }
    if (i < N_G)     d_gcnt[i] = 0;
    if (i < N_G * N_OUT) d_P[i] = 0.f;
}

__device__ __forceinline__ unsigned short f2bf_hi(float w) {
    return (unsigned short)__bfloat16_as_ushort(__float2bfloat16(w));
}

__device__ __forceinline__ void w1pack_body(int idx, const float* __restrict__ W1) {
    if (idx >= 8192) return;
    int q = idx & 3, ks = (idx >> 2) & 7, j = idx >> 5;
    int k0 = ks * 16;
    int ka = k0 + 2 * q;
    int kb = k0 + 8 + 2 * q;
    float wa0 = W1[ka * HID + j],       wa1 = W1[(ka + 1) * HID + j];
    float wb0 = W1[kb * HID + j],       wb1 = W1[(kb + 1) * HID + j];
    unsigned short ha0 = f2bf_hi(wa0), ha1 = f2bf_hi(wa1);
    unsigned short hb0 = f2bf_hi(wb0), hb1 = f2bf_hi(wb1);
    float ra0 = wa0 - __bfloat162float(__ushort_as_bfloat16(ha0));
    float ra1 = wa1 - __bfloat162float(__ushort_as_bfloat16(ha1));
    float rb0 = wb0 - __bfloat162float(__ushort_as_bfloat16(hb0));
    float rb1 = wb1 - __bfloat162float(__ushort_as_bfloat16(hb1));
    uint4 o;
    o.x = (unsigned)f2bf_hi(wa0) | ((unsigned)ha1 << 16);
    o.x = (unsigned)ha0 | ((unsigned)ha1 << 16);
    o.y = (unsigned)hb0 | ((unsigned)hb1 << 16);
    o.z = (unsigned)f2bf_hi(ra0) | ((unsigned)f2bf_hi(ra1) << 16);
    o.w = (unsigned)f2bf_hi(rb0) | ((unsigned)f2bf_hi(rb1) << 16);
    d_W1q[idx] = o;
}

__device__ __forceinline__ void mk_body(int h, const float* __restrict__ W2,
                                        const float* __restrict__ Wlin) {
    float acc[N_OUT];
    #pragma unroll
    for (int c = 0; c < N_OUT; c++) acc[c] = 0.f;
    for (int k = 0; k < HID; k++) {
        float w = W2[h * HID + k];
        #pragma unroll
        for (int c = 0; c < N_OUT; c++) acc[c] += w * Wlin[k * N_OUT + c];
    }
    #pragma unroll
    for (int c = 0; c < N_OUT; c++) d_M[h * N_OUT + c] = acc[c];
}

// ---------------- mixA: counts || RNG part 1 ----------------
__global__ __launch_bounds__(256) void mixA_kernel(const int* __restrict__ dst,
                                                   const int* __restrict__ batch,
                                                   const float* __restrict__ x, Keys keys) {
    int bid = blockIdx.x, tid = threadIdx.x;
    if (bid < RNG1_BLOCKS) {
        rng_body(bid * 256 + tid, x, keys);
    } else {
        int e = (bid - RNG1_BLOCKS) * 256 + tid;
        if (e < N_EDGES) atomicAdd(&d_degcnt[dst[e]], 1);
        if (e < N_NODES) atomicAdd(&d_gcnt[batch[e]], 1);
    }
}

// ---------------- 3-phase scan ----------------
__global__ void scanP1() {
    __shared__ int wsum[32];
    int b = blockIdx.x, tid = threadIdx.x, lane = tid & 31, w = tid >> 5;
    int i = b * SCAN_TPB + tid;
    int v = (i < N_NODES) ? d_degcnt[i] : 0;
    int s = v;
    #pragma unroll
    for (int off = 16; off > 0; off >>= 1) s += __shfl_down_sync(0xFFFFFFFFu, s, off);
    if (lane == 0) wsum[w] = s;
    __syncthreads();
    if (w == 0) {
        int t = (lane < SCAN_TPB / 32) ? wsum[lane] : 0;
        #pragma unroll
        for (int off = 16; off > 0; off >>= 1) t += __shfl_down_sync(0xFFFFFFFFu, t, off);
        if (lane == 0) d_bsum[b] = t;
    }
}

__global__ void scanP2() {
    __shared__ int sh[64];
    int tid = threadIdx.x;   // 64 threads
    sh[tid] = (tid < SCAN_NB) ? d_bsum[tid] : 0;
    __syncthreads();
    for (int off = 1; off < 64; off <<= 1) {
        int t = (tid >= off) ? sh[tid - off] : 0;
        __syncthreads();
        sh[tid] += t;
        __syncthreads();
    }
    if (tid < SCAN_NB) d_bsum[tid] = sh[tid] - ((tid < SCAN_NB) ? d_degcnt[0] : 0) * 0
                                      - (tid < SCAN_NB ? 0 : 0);
    // exclusive: subtract own value
    __syncthreads();
    if (tid < SCAN_NB) {
        int incl = sh[tid];
        int own = (tid == 0) ? incl : incl - sh[tid - 1];
        d_bsum[tid] = incl - own;
    }
    if (tid == 63) d_rowptr[N_NODES] = sh[SCAN_NB - 1];
}

__global__ void scanP3() {
    __shared__ int wsum[32];
    int b = blockIdx.x, tid = threadIdx.x, lane = tid & 31, w = tid >> 5;
    int i = b * SCAN_TPB + tid;
    int v = (i < N_NODES) ? d_degcnt[i] : 0;
    int xs = v;
    #pragma unroll
    for (int off = 1; off < 32; off <<= 1) {
        int y = __shfl_up_sync(0xFFFFFFFFu, xs, off);
        if (lane >= off) xs += y;
    }
    if (lane == 31) wsum[w] = xs;
    __syncthreads();
    if (w == 0) {
        int s = wsum[lane];
        #pragma unroll
        for (int off = 1; off < 32; off <<= 1) {
            int y = __shfl_up_sync(0xFFFFFFFFu, s, off);
            if (lane >= off) s += y;
        }
        wsum[lane] = s;
    }
    __syncthreads();
    int pre = (w > 0 ? wsum[w - 1] : 0) + (xs - v) + d_bsum[b];
    if (i < N_NODES) d_rowptr[i] = pre;
}

// ---------------- mixB: csr_fill || preps || w1pack || mk || RNG part 2 ----------------
__global__ __launch_bounds__(256) void mixB_kernel(const int* __restrict__ src,
                                                   const int* __restrict__ dst,
                                                   const float* __restrict__ x,
                                                   const float* __restrict__ W1,
                                                   const float* __restrict__ W2,
                                                   const float* __restrict__ Wlin,
                                                   Keys keys) {
    int bid = blockIdx.x, tid = threadIdx.x;
    if (bid < RNG2_BLOCKS) {
        rng_body(RNG1_END + bid * 256 + tid, x, keys);
        return;
    }
    bid -= RNG2_BLOCKS;
    if (bid < FILL_BLOCKS) {
        int e = bid * 256 + tid;
        if (e < N_EDGES) {
            int d = dst[e];
            int p = atomicAdd(&d_cursor[d], 1);
            d_colsrc[d_rowptr[d] + p] = src[e];
        }
        return;
    }
    bid -= FILL_BLOCKS;
    if (bid < PREP_BLOCKS) {
        int n = bid * 256 + tid;
        if (n < N_NODES) {
            int c = d_degcnt[n];
            int cm = c > 1 ? c : 1;
            d_invdeg[n] = 1.0f / (float)cm;
            d_invsqrt[n] = 1.0f / sqrtf((float)(c + 1));
        }
        if (n < N_G) {
            int c = d_gcnt[n];
            d_invcnt[n] = 1.0f / (float)(c > 1 ? c : 1);
        }
        return;
    }
    bid -= PREP_BLOCKS;
    if (bid < W1P_BLOCKS) {
        w1pack_body(bid * 256 + tid, W1);
        return;
    }
    bid -= W1P_BLOCKS;
    if (bid == 0) mk_body(tid, W2, Wlin);
}

// ---------------- warp-mma helpers ----------------
__device__ __forceinline__ void mma_bf16(float* d, const unsigned* a, unsigned b0, unsigned b1) {
    asm volatile(
        "mma.sync.aligned.m16n8k16.row.col.f32.bf16.bf16.f32 "
        "{%0,%1,%2,%3}, {%4,%5,%6,%7}, {%8,%9}, {%0,%1,%2,%3};"
        : "+f"(d[0]), "+f"(d[1]), "+f"(d[2]), "+f"(d[3])
        : "r"(a[0]), "r"(a[1]), "r"(a[2]), "r"(a[3]), "r"(b0), "r"(b1));
}

__device__ __forceinline__ void ldmatrix4(unsigned* r, uint32_t addr) {
    asm volatile("ldmatrix.sync.aligned.m8n8.x4.shared.b16 {%0,%1,%2,%3}, [%4];"
        : "=r"(r[0]), "=r"(r[1]), "=r"(r[2]), "=r"(r[3]) : "r"(addr));
}

// ---------------- fused time-loop megakernel ----------------
#define A_STRIDE 136
#define SMEM_BYTES (TILE * A_STRIDE * 2)

__global__ __launch_bounds__(512) void fused_kernel() {
    __shared__ char smem[SMEM_BYTES];
    unsigned short* Aimg = (unsigned short*)smem;
    const int tid = threadIdx.x;
    const int wid = tid >> 5, lane = tid & 31;
    const int tile0 = blockIdx.x * TILE;
    const int rg = wid >> 2, cg = wid & 3;
    const int q = lane & 3, l4 = lane >> 2;

    uint32_t sbA;
    asm("{ .reg .u64 t; cvta.to.shared.u64 t, %1; cvt.u32.u64 %0, t; }" : "=r"(sbA) : "l"(smem));

    // carry: v' = (count + deg*v) * (0.5*invdeg) == 0.5*h + 0.5*v
    float hidg[4], dcar[4];
    #pragma unroll
    for (int r = 0; r < 4; r++) {
        int lr = rg * 32 + (r >> 1) * 16 + (r & 1) * 8 + l4;
        int n = tile0 + lr;
        if (n < N_NODES) {
            int c = d_degcnt[n];
            int cm = c > 1 ? c : 1;
            hidg[r] = 0.5f * d_invdeg[n];
            dcar[r] = (float)cm;
        } else { hidg[r] = 0.f; dcar[r] = 0.f; }
    }

    unsigned Spk[8];
    #pragma unroll
    for (int i = 0; i < 8; i++) Spk[i] = 0u;

    float acc[2][8][4];
    #pragma unroll
    for (int rb = 0; rb < 2; rb++)
        #pragma unroll
        for (int nt = 0; nt < 8; nt++)
            #pragma unroll
            for (int k = 0; k < 4; k++) acc[rb][nt][k] = 0.f;

    const uint32_t aAddr0 = sbA + (uint32_t)(((rg * 32 + (lane & 15)) * A_STRIDE + (lane >> 4) * 8) * 2);
    const uint32_t aAddr1 = aAddr0 + 16 * A_STRIDE * 2;

    for (int t = 0; t < T_STEPS; t++) {
        // ---- aggregation: warp wid handles nodes [wid*8, wid*8+8), unroll 4 ----
        const uint4* xb = d_xtbits4 + (size_t)t * N_NODES;
        #pragma unroll 1
        for (int i = 0; i < 8; i++) {
            int m = wid * 8 + i;
            int n = tile0 + m;
            int c0 = 0, c1 = 0, c2 = 0, c3 = 0;
            if (n < N_NODES) {
                int beg = __ldg(&d_rowptr[n]), end = __ldg(&d_rowptr[n + 1]);
                int e = beg;
                #pragma unroll 1
                for (; e + 4 <= end; e += 4) {
                    int s0 = __ldg(&d_colsrc[e]),     s1 = __ldg(&d_colsrc[e + 1]);
                    int s2 = __ldg(&d_colsrc[e + 2]), s3 = __ldg(&d_colsrc[e + 3]);
                    uint4 w0 = __ldg(xb + s0), w1 = __ldg(xb + s1);
                    uint4 w2 = __ldg(xb + s2), w3 = __ldg(xb + s3);
                    c0 += ((w0.x >> lane) & 1) + ((w1.x >> lane) & 1) + ((w2.x >> lane) & 1) + ((w3.x >> lane) & 1);
                    c1 += ((w0.y >> lane) & 1) + ((w1.y >> lane) & 1) + ((w2.y >> lane) & 1) + ((w3.y >> lane) & 1);
                    c2 += ((w0.z >> lane) & 1) + ((w1.z >> lane) & 1) + ((w2.z >> lane) & 1) + ((w3.z >> lane) & 1);
                    c3 += ((w0.w >> lane) & 1) + ((w1.w >> lane) & 1) + ((w2.w >> lane) & 1) + ((w3.w >> lane) & 1);
                }
                for (; e < end; e++) {
                    uint4 wv = __ldg(xb + __ldg(&d_colsrc[e]));
                    c0 += (wv.x >> lane) & 1;
                    c1 += (wv.y >> lane) & 1;
                    c2 += (wv.z >> lane) & 1;
                    c3 += (wv.w >> lane) & 1;
                }
            }
            Aimg[m * A_STRIDE + lane]      = (unsigned short)(__float_as_uint((float)c0) >> 16);
            Aimg[m * A_STRIDE + 32 + lane] = (unsigned short)(__float_as_uint((float)c1) >> 16);
            Aimg[m * A_STRIDE + 64 + lane] = (unsigned short)(__float_as_uint((float)c2) >> 16);
            Aimg[m * A_STRIDE + 96 + lane] = (unsigned short)(__float_as_uint((float)c3) >> 16);
        }
        __syncthreads();

        // ---- warp GEMM accumulating onto acc (= deg*v carried in) ----
        #pragma unroll
        for (int ks = 0; ks < 8; ks++) {
            unsigned a0[4], a1[4];
            ldmatrix4(a0, aAddr0 + (uint32_t)(ks * 32));
            ldmatrix4(a1, aAddr1 + (uint32_t)(ks * 32));
            #pragma unroll
            for (int nt = 0; nt < 8; nt++) {
                int j = cg * 64 + nt * 8 + l4;
                uint4 B = __ldg(&d_W1q[(j * 8 + ks) * 4 + q]);
                mma_bf16(acc[0][nt], a0, B.x, B.y);
                mma_bf16(acc[1][nt], a1, B.x, B.y);
                mma_bf16(acc[0][nt], a0, B.z, B.w);
                mma_bf16(acc[1][nt], a1, B.z, B.w);
            }
        }

        // ---- LIF epilogue fully in registers ----
        #pragma unroll
        for (int rb = 0; rb < 2; rb++) {
            #pragma unroll
            for (int nt = 0; nt < 8; nt++) {
                #pragma unroll
                for (int h8 = 0; h8 < 2; h8++) {
                    const int r = rb * 2 + h8;
                    #pragma unroll
                    for (int p = 0; p < 2; p++) {
                        float vn = acc[rb][nt][h8 * 2 + p] * hidg[r];
                        const int slot = r * 16 + nt * 2 + p;
                        if (vn >= 0.25f) { Spk[slot >> 3] += 1u << ((slot & 7) * 4); vn = 0.f; }
                        acc[rb][nt][h8 * 2 + p] = vn * dcar[r];
                    }
                }
            }
        }
        __syncthreads();
    }

    // ---- fused readout: y = S @ M ----
    float* Msm  = (float*)smem;
    float* yacc = (float*)(smem + 10240);
    for (int i = tid; i < HID * N_OUT; i += 512) Msm[i] = d_M[i];
    for (int i = tid; i < TILE * N_OUT; i += 512) yacc[i] = 0.f;
    __syncthreads();

    #pragma unroll
    for (int r = 0; r < 4; r++) {
        float py[N_OUT];
        #pragma unroll
        for (int c = 0; c < N_OUT; c++) py[c] = 0.f;
        #pragma unroll
        for (int nt = 0; nt < 8; nt++) {
            #pragma unroll
            for (int p = 0; p < 2; p++) {
                const int slot = r * 16 + nt * 2 + p;
                float s = (float)((Spk[slot >> 3] >> ((slot & 7) * 4)) & 15u);
                const float* Mr = Msm + (cg * 64 + nt * 8 + q * 2 + p) * N_OUT;
                #pragma unroll
                for (int c = 0; c < N_OUT; c++) py[c] += s * Mr[c];
            }
        }
        #pragma unroll
        for (int c = 0; c < N_OUT; c++) {
            py[c] += __shfl_xor_sync(0xFFFFFFFFu, py[c], 1);
            py[c] += __shfl_xor_sync(0xFFFFFFFFu, py[c], 2);
        }
        if (q == 0) {
            int lr = rg * 32 + (r >> 1) * 16 + (r & 1) * 8 + l4;
            #pragma unroll
            for (int c = 0; c < N_OUT; c++)
                atomicAdd(&yacc[lr * N_OUT + c], py[c]);
        }
    }
    __syncthreads();

    for (int i = tid; i < TILE * N_OUT; i += 512) {
        int node = tile0 + i / N_OUT;
        if (node < N_NODES) d_y[(size_t)node * N_OUT + (i % N_OUT)] = yacc[i];
    }
}

// ---------------- pool + final ----------------
__global__ void pool_kernel(const int* __restrict__ batch) {
    int n = blockIdx.x * blockDim.x + threadIdx.x;
    if (n >= N_NODES) return;
    float acc[N_OUT];
    #pragma unroll
    for (int c = 0; c < N_OUT; c++) acc[c] = 0.f;
    int beg = d_rowptr[n], end = d_rowptr[n + 1];
    int e = beg;
    for (; e + 2 <= end; e += 2) {
        int s0 = __ldg(&d_colsrc[e]), s1 = __ldg(&d_colsrc[e + 1]);
        float w0 = __ldg(&d_invsqrt[s0]), w1 = __ldg(&d_invsqrt[s1]);
        const float* y0 = d_y + (size_t)s0 * N_OUT;
        const float* y1 = d_y + (size_t)s1 * N_OUT;
        #pragma unroll
        for (int c = 0; c < N_OUT; c++) acc[c] += w0 * __ldg(&y0[c]) + w1 * __ldg(&y1[c]);
    }
    for (; e < end; e++) {
        int s = __ldg(&d_colsrc[e]);
        float ws = __ldg(&d_invsqrt[s]);
        const float* yp = d_y + (size_t)s * N_OUT;
        #pragma unroll
        for (int c = 0; c < N_OUT; c++) acc[c] += ws * __ldg(&yp[c]);
    }
    float isn = d_invsqrt[n];
    const float* yn = d_y + (size_t)n * N_OUT;
    int g = batch[n];
    float sc = d_invcnt[g];
    #pragma unroll
    for (int c = 0; c < N_OUT; c++) {
        float z = acc[c] * isn + isn * isn * yn[c];
        atomicAdd(&d_P[g * N_OUT + c], z * sc);
    }
}

__global__ void final_kernel(const float* __restrict__ b2,
                             const float* __restrict__ Wlin,
                             const float* __restrict__ blin,
                             float* __restrict__ out) {
    int idx = blockIdx.x * blockDim.x + threadIdx.x;
    if (idx >= N_G * N_OUT) return;
    int c = idx % N_OUT;
    float b2w = 0.f;
    for (int k = 0; k < HID; k++) b2w += b2[k] * Wlin[k * N_OUT + c];
    out[idx] = d_P[idx] / 15.0f + b2w + blin[c];
}

// ---------------- launch ----------------
extern "C" void kernel_launch(void* const* d_in, const int* in_sizes, int n_in,
                              void* d_out, int out_size) {
    const float *x = 0, *W1 = 0, *W2 = 0, *b2 = 0, *Wlin = 0, *blin = 0;
    const int *src = 0, *dst = 0, *batch = 0;
    for (int i = 0; i < n_in; i++) {
        int s = in_sizes[i];
        void* p = d_in[i];
        if (s == N_NODES * F_IN)       x = (const float*)p;
        else if (s == F_IN * HID)      W1 = (const float*)p;
        else if (s == HID * HID)       W2 = (const float*)p;
        else if (s == HID)             b2 = (const float*)p;
        else if (s == HID * N_OUT)     Wlin = (const float*)p;
        else if (s == N_OUT)           blin = (const float*)p;
        else if (s == N_EDGES)         { if (!src) src = (const int*)p; else dst = (const int*)p; }
        else if (s == N_NODES)         batch = (const int*)p;
    }

    Keys keys;
    for (int t = 0; t < T_STEPS; t++) {
        uint32_t o0, o1;
        threefry_pair_host(0u, 42u, 0u, (uint32_t)t, &o0, &o1);
        keys.k0[t] = o0; keys.k1[t] = o1;
    }

    init_kernel<<<(N_NODES + 255) / 256, 256>>>();
    mixA_kernel<<<RNG1_BLOCKS + CNT_BLOCKS, 256>>>(dst, batch, x, keys);
    scanP1<<<SCAN_NB, SCAN_TPB>>>();
    scanP2<<<1, 64>>>();
    scanP3<<<SCAN_NB, SCAN_TPB>>>();
    mixB_kernel<<<RNG2_BLOCKS + FILL_BLOCKS + PREP_BLOCKS + W1P_BLOCKS + 1, 256>>>(
        src, dst, x, W1, W2, Wlin, keys);
    fused_kernel<<<N_TILES, 512>>>();
    pool_kernel<<<(N_NODES + 255) / 256, 256>>>(batch);
    final_kernel<<<(N_G * N_OUT + 255) / 256, 256>>>(b2, Wlin, blin, (float*)d_out);
}

// round 10
// speedup vs baseline: 1.0989x; 1.0989x over previous
#include <cuda_runtime.h>
#include <cuda_bf16.h>
#include <stdint.h>
#include <math.h>

#define N_NODES 50000
#define N_EDGES 800000
#define F_IN    128
#define HID     256
#define N_OUT   10
#define N_G     128
#define T_STEPS 15
#define TILE    128
#define N_TILES 391   // ceil(50000/128)

#define RNG_TOTAL   (T_STEPS * N_NODES * 4)          // 3,000,000
#define RNG1_BLOCKS 7000
#define RNG1_END    (RNG1_BLOCKS * 256)
#define RNG2_BLOCKS ((RNG_TOTAL - RNG1_END + 255) / 256)
#define CNT_BLOCKS  ((N_EDGES + 255) / 256)
#define FILL_BLOCKS ((N_EDGES + 255) / 256)
#define PREP_BLOCKS ((N_NODES + 255) / 256)
#define W1P_BLOCKS  32
#define SCAN_TPB    1024
#define SCAN_NB     ((N_NODES + SCAN_TPB - 1) / SCAN_TPB)

// ---------------- device scratch ----------------
__device__ uint4  d_xtbits4[(size_t)T_STEPS * N_NODES];  // 12 MB bitpacked x_t
__device__ uint4  d_W1q[8192];                           // 128KB packed bf16 hi/lo fragments
__device__ int    d_degcnt[N_NODES];
__device__ int    d_rowptr[N_NODES + 1];
__device__ int    d_cursor[N_NODES];
__device__ int    d_colsrc[N_EDGES];
__device__ int    d_bsum[SCAN_NB];
__device__ float  d_invdeg[N_NODES];
__device__ float  d_invsqrt[N_NODES];
__device__ int    d_gcnt[N_G];
__device__ float  d_invcnt[N_G];
__device__ float  d_M[HID * N_OUT];
__device__ float  d_y[(size_t)N_NODES * N_OUT];
__device__ float  d_P[N_G * N_OUT];

struct Keys { unsigned k0[T_STEPS]; unsigned k1[T_STEPS]; };

// ---------------- host threefry for subkeys ----------------
static void threefry_pair_host(uint32_t k0, uint32_t k1, uint32_t x0, uint32_t x1,
                               uint32_t* o0, uint32_t* o1) {
    uint32_t ks2 = k0 ^ k1 ^ 0x1BD11BDAu;
    x0 += k0; x1 += k1;
#define HR(R) { x0 += x1; x1 = (x1 << R) | (x1 >> (32 - R)); x1 ^= x0; }
    HR(13) HR(15) HR(26) HR(6)
    x0 += k1; x1 += ks2 + 1u;
    HR(17) HR(29) HR(16) HR(24)
    x0 += ks2; x1 += k0 + 2u;
    HR(13) HR(15) HR(26) HR(6)
    x0 += k0; x1 += k1 + 3u;
    HR(17) HR(29) HR(16) HR(24)
    x0 += k1; x1 += ks2 + 4u;
    HR(13) HR(15) HR(26) HR(6)
    x0 += ks2; x1 += k0 + 5u;
#undef HR
    *o0 = x0; *o1 = x1;
}

// ---------------- device RNG body ----------------
#define DR(R) { x0 += x1; x1 = __funnelshift_l(x1, x1, R); x1 ^= x0; }

__device__ __forceinline__ void rng_body(int gid, const float* __restrict__ x, const Keys& keys) {
    if (gid >= RNG_TOTAL) return;
    int w  = gid & 3;
    int nw = gid >> 2;
    int n  = nw % N_NODES;
    int t  = nw / N_NODES;
    const unsigned k0 = keys.k0[t];
    const unsigned k1 = keys.k1[t];
    const unsigned ks2 = k0 ^ k1 ^ 0x1BD11BDAu;
    const unsigned base = (unsigned)(n * F_IN + w * 32);
    const float* xr = x + n * F_IN + w * 32;
    unsigned outw = 0u;
    #pragma unroll 4
    for (int b = 0; b < 32; b++) {
        unsigned x0 = k0;
        unsigned x1 = base + (unsigned)b + k1;
        DR(13) DR(15) DR(26) DR(6)
        x0 += k1;  x1 += ks2 + 1u;
        DR(17) DR(29) DR(16) DR(24)
        x0 += ks2; x1 += k0 + 2u;
        DR(13) DR(15) DR(26) DR(6)
        x0 += k0;  x1 += k1 + 3u;
        DR(17) DR(29) DR(16) DR(24)
        x0 += k1;  x1 += ks2 + 4u;
        DR(13) DR(15) DR(26) DR(6)
        x0 += ks2; x1 += k0 + 5u;
        unsigned bits = x0 ^ x1;
        float u = __uint_as_float((bits >> 9) | 0x3f800000u) - 1.0f;
        if (u < xr[b]) outw |= (1u << b);
    }
    ((unsigned*)d_xtbits4)[gid] = outw;
}
#undef DR

// ---------------- prep bodies ----------------
__global__ void init_kernel() {
    int i = blockIdx.x * blockDim.x + threadIdx.x;
    if (i < N_NODES) { d_degcnt[i] = 0; d_cursor[i] = 0; }
    if (i < N_G)     d_gcnt[i] = 0;
    if (i < N_G * N_OUT) d_P[i] = 0.f;
}

__device__ __forceinline__ unsigned short f2bf_hi(float w) {
    return (unsigned short)__bfloat16_as_ushort(__float2bfloat16(w));
}

__device__ __forceinline__ void w1pack_body(int idx, const float* __restrict__ W1) {
    if (idx >= 8192) return;
    int q = idx & 3, ks = (idx >> 2) & 7, j = idx >> 5;
    int k0 = ks * 16;
    int ka = k0 + 2 * q;
    int kb = k0 + 8 + 2 * q;
    float wa0 = W1[ka * HID + j],       wa1 = W1[(ka + 1) * HID + j];
    float wb0 = W1[kb * HID + j],       wb1 = W1[(kb + 1) * HID + j];
    unsigned short ha0 = f2bf_hi(wa0), ha1 = f2bf_hi(wa1);
    unsigned short hb0 = f2bf_hi(wb0), hb1 = f2bf_hi(wb1);
    float ra0 = wa0 - __bfloat162float(__ushort_as_bfloat16(ha0));
    float ra1 = wa1 - __bfloat162float(__ushort_as_bfloat16(ha1));
    float rb0 = wb0 - __bfloat162float(__ushort_as_bfloat16(hb0));
    float rb1 = wb1 - __bfloat162float(__ushort_as_bfloat16(hb1));
    uint4 o;
    o.x = (unsigned)ha0 | ((unsigned)ha1 << 16);
    o.y = (unsigned)hb0 | ((unsigned)hb1 << 16);
    o.z = (unsigned)f2bf_hi(ra0) | ((unsigned)f2bf_hi(ra1) << 16);
    o.w = (unsigned)f2bf_hi(rb0) | ((unsigned)f2bf_hi(rb1) << 16);
    d_W1q[idx] = o;
}

__device__ __forceinline__ void mk_body(int h, const float* __restrict__ W2,
                                        const float* __restrict__ Wlin) {
    float acc[N_OUT];
    #pragma unroll
    for (int c = 0; c < N_OUT; c++) acc[c] = 0.f;
    for (int k = 0; k < HID; k++) {
        float w = W2[h * HID + k];
        #pragma unroll
        for (int c = 0; c < N_OUT; c++) acc[c] += w * Wlin[k * N_OUT + c];
    }
    #pragma unroll
    for (int c = 0; c < N_OUT; c++) d_M[h * N_OUT + c] = acc[c];
}

// ---------------- mixA: counts || RNG part 1 ----------------
__global__ __launch_bounds__(256) void mixA_kernel(const int* __restrict__ dst,
                                                   const int* __restrict__ batch,
                                                   const float* __restrict__ x, Keys keys) {
    int bid = blockIdx.x, tid = threadIdx.x;
    if (bid < RNG1_BLOCKS) {
        rng_body(bid * 256 + tid, x, keys);
    } else {
        int e = (bid - RNG1_BLOCKS) * 256 + tid;
        if (e < N_EDGES) atomicAdd(&d_degcnt[dst[e]], 1);
        if (e < N_NODES) atomicAdd(&d_gcnt[batch[e]], 1);
    }
}

// ---------------- 3-phase scan ----------------
__global__ void scanP1() {
    __shared__ int wsum[32];
    int b = blockIdx.x, tid = threadIdx.x, lane = tid & 31, w = tid >> 5;
    int i = b * SCAN_TPB + tid;
    int v = (i < N_NODES) ? d_degcnt[i] : 0;
    int s = v;
    #pragma unroll
    for (int off = 16; off > 0; off >>= 1) s += __shfl_down_sync(0xFFFFFFFFu, s, off);
    if (lane == 0) wsum[w] = s;
    __syncthreads();
    if (w == 0) {
        int t = (lane < SCAN_TPB / 32) ? wsum[lane] : 0;
        #pragma unroll
        for (int off = 16; off > 0; off >>= 1) t += __shfl_down_sync(0xFFFFFFFFu, t, off);
        if (lane == 0) d_bsum[b] = t;
    }
}

__global__ void scanP2() {
    __shared__ int sh[64];
    int tid = threadIdx.x;   // 64 threads
    sh[tid] = (tid < SCAN_NB) ? d_bsum[tid] : 0;
    __syncthreads();
    for (int off = 1; off < 64; off <<= 1) {
        int t = (tid >= off) ? sh[tid - off] : 0;
        __syncthreads();
        sh[tid] += t;
        __syncthreads();
    }
    if (tid < SCAN_NB) {
        int incl = sh[tid];
        int own = (tid == 0) ? incl : incl - sh[tid - 1];
        d_bsum[tid] = incl - own;
    }
    if (tid == 63) d_rowptr[N_NODES] = sh[SCAN_NB - 1];
}

__global__ void scanP3() {
    __shared__ int wsum[32];
    int b = blockIdx.x, tid = threadIdx.x, lane = tid & 31, w = tid >> 5;
    int i = b * SCAN_TPB + tid;
    int v = (i < N_NODES) ? d_degcnt[i] : 0;
    int xs = v;
    #pragma unroll
    for (int off = 1; off < 32; off <<= 1) {
        int y = __shfl_up_sync(0xFFFFFFFFu, xs, off);
        if (lane >= off) xs += y;
    }
    if (lane == 31) wsum[w] = xs;
    __syncthreads();
    if (w == 0) {
        int s = wsum[lane];
        #pragma unroll
        for (int off = 1; off < 32; off <<= 1) {
            int y = __shfl_up_sync(0xFFFFFFFFu, s, off);
            if (lane >= off) s += y;
        }
        wsum[lane] = s;
    }
    __syncthreads();
    int pre = (w > 0 ? wsum[w - 1] : 0) + (xs - v) + d_bsum[b];
    if (i < N_NODES) d_rowptr[i] = pre;
}

// ---------------- mixB: csr_fill || preps || w1pack || mk || RNG part 2 ----------------
__global__ __launch_bounds__(256) void mixB_kernel(const int* __restrict__ src,
                                                   const int* __restrict__ dst,
                                                   const float* __restrict__ x,
                                                   const float* __restrict__ W1,
                                                   const float* __restrict__ W2,
                                                   const float* __restrict__ Wlin,
                                                   Keys keys) {
    int bid = blockIdx.x, tid = threadIdx.x;
    if (bid < RNG2_BLOCKS) {
        rng_body(RNG1_END + bid * 256 + tid, x, keys);
        return;
    }
    bid -= RNG2_BLOCKS;
    if (bid < FILL_BLOCKS) {
        int e = bid * 256 + tid;
        if (e < N_EDGES) {
            int d = dst[e];
            int p = atomicAdd(&d_cursor[d], 1);
            d_colsrc[d_rowptr[d] + p] = src[e];
        }
        return;
    }
    bid -= FILL_BLOCKS;
    if (bid < PREP_BLOCKS) {
        int n = bid * 256 + tid;
        if (n < N_NODES) {
            int c = d_degcnt[n];
            int cm = c > 1 ? c : 1;
            d_invdeg[n] = 1.0f / (float)cm;
            d_invsqrt[n] = 1.0f / sqrtf((float)(c + 1));
        }
        if (n < N_G) {
            int c = d_gcnt[n];
            d_invcnt[n] = 1.0f / (float)(c > 1 ? c : 1);
        }
        return;
    }
    bid -= PREP_BLOCKS;
    if (bid < W1P_BLOCKS) {
        w1pack_body(bid * 256 + tid, W1);
        return;
    }
    bid -= W1P_BLOCKS;
    if (bid == 0) mk_body(tid, W2, Wlin);
}

// ---------------- warp-mma helpers ----------------
__device__ __forceinline__ void mma_bf16(float* d, const unsigned* a, unsigned b0, unsigned b1) {
    asm volatile(
        "mma.sync.aligned.m16n8k16.row.col.f32.bf16.bf16.f32 "
        "{%0,%1,%2,%3}, {%4,%5,%6,%7}, {%8,%9}, {%0,%1,%2,%3};"
        : "+f"(d[0]), "+f"(d[1]), "+f"(d[2]), "+f"(d[3])
        : "r"(a[0]), "r"(a[1]), "r"(a[2]), "r"(a[3]), "r"(b0), "r"(b1));
}

__device__ __forceinline__ void ldmatrix4(unsigned* r, uint32_t addr) {
    asm volatile("ldmatrix.sync.aligned.m8n8.x4.shared.b16 {%0,%1,%2,%3}, [%4];"
        : "=r"(r[0]), "=r"(r[1]), "=r"(r[2]), "=r"(r[3]) : "r"(addr));
}

// ---------------- fused time-loop megakernel ----------------
// dynamic smem: A double buffer, 2 x (128 x 136 bf16) = 2 x 34816 B = 69632 B.
// Quad q (warps 4q..4q+3) writes A rows [32q,32q+32) and is the ONLY reader of
// those rows (ldmatrix) -> per-quad named barrier replaces CTA-wide syncthreads.
// After the t-loop the buffer is reused for readout (M + yacc).
#define A_STRIDE 136
#define A_BUF_BYTES (TILE * A_STRIDE * 2)
#define SMEM_DYN (2 * A_BUF_BYTES)

extern __shared__ char dsm[];

__global__ __launch_bounds__(512) void fused_kernel() {
    const int tid = threadIdx.x;
    const int wid = tid >> 5, lane = tid & 31;
    const int tile0 = blockIdx.x * TILE;
    const int rg = wid >> 2, cg = wid & 3;   // quad = rg
    const int q = lane & 3, l4 = lane >> 2;

    uint32_t sbA;
    asm("{ .reg .u64 t; cvta.to.shared.u64 t, %1; cvt.u32.u64 %0, t; }" : "=r"(sbA) : "l"(dsm));

    // carry: v' = (count + deg*v) * (0.5*invdeg) == 0.5*h + 0.5*v
    float hidg[4], dcar[4];
    #pragma unroll
    for (int r = 0; r < 4; r++) {
        int lr = rg * 32 + (r >> 1) * 16 + (r & 1) * 8 + l4;
        int n = tile0 + lr;
        if (n < N_NODES) {
            int c = d_degcnt[n];
            int cm = c > 1 ? c : 1;
            hidg[r] = 0.5f * d_invdeg[n];
            dcar[r] = (float)cm;
        } else { hidg[r] = 0.f; dcar[r] = 0.f; }
    }

    unsigned Spk[8];
    #pragma unroll
    for (int i = 0; i < 8; i++) Spk[i] = 0u;

    float acc[2][8][4];
    #pragma unroll
    for (int rb = 0; rb < 2; rb++)
        #pragma unroll
        for (int nt = 0; nt < 8; nt++)
            #pragma unroll
            for (int k = 0; k < 4; k++) acc[rb][nt][k] = 0.f;

    const uint32_t aOff0 = (uint32_t)(((rg * 32 + (lane & 15)) * A_STRIDE + (lane >> 4) * 8) * 2);
    const uint32_t aOff1 = aOff0 + 16 * A_STRIDE * 2;

    for (int t = 0; t < T_STEPS; t++) {
        const uint32_t bufB = (uint32_t)((t & 1) * A_BUF_BYTES);
        unsigned short* Aimg = (unsigned short*)(dsm + bufB);

        // ---- aggregation: warp wid fills its 8 rows, MLP=8 ----
        const uint4* xb = d_xtbits4 + (size_t)t * N_NODES;
        #pragma unroll 1
        for (int i = 0; i < 8; i++) {
            int m = wid * 8 + i;
            int n = tile0 + m;
            int c0 = 0, c1 = 0, c2 = 0, c3 = 0;
            if (n < N_NODES) {
                int beg = __ldg(&d_rowptr[n]), end = __ldg(&d_rowptr[n + 1]);
                int e = beg;
                #pragma unroll 1
                for (; e + 8 <= end; e += 8) {
                    int s0 = __ldg(&d_colsrc[e]),     s1 = __ldg(&d_colsrc[e + 1]);
                    int s2 = __ldg(&d_colsrc[e + 2]), s3 = __ldg(&d_colsrc[e + 3]);
                    int s4 = __ldg(&d_colsrc[e + 4]), s5 = __ldg(&d_colsrc[e + 5]);
                    int s6 = __ldg(&d_colsrc[e + 6]), s7 = __ldg(&d_colsrc[e + 7]);
                    uint4 w0 = __ldg(xb + s0), w1 = __ldg(xb + s1);
                    uint4 w2 = __ldg(xb + s2), w3 = __ldg(xb + s3);
                    uint4 w4 = __ldg(xb + s4), w5 = __ldg(xb + s5);
                    uint4 w6 = __ldg(xb + s6), w7 = __ldg(xb + s7);
                    c0 += ((w0.x >> lane) & 1) + ((w1.x >> lane) & 1) + ((w2.x >> lane) & 1) + ((w3.x >> lane) & 1)
                        + ((w4.x >> lane) & 1) + ((w5.x >> lane) & 1) + ((w6.x >> lane) & 1) + ((w7.x >> lane) & 1);
                    c1 += ((w0.y >> lane) & 1) + ((w1.y >> lane) & 1) + ((w2.y >> lane) & 1) + ((w3.y >> lane) & 1)
                        + ((w4.y >> lane) & 1) + ((w5.y >> lane) & 1) + ((w6.y >> lane) & 1) + ((w7.y >> lane) & 1);
                    c2 += ((w0.z >> lane) & 1) + ((w1.z >> lane) & 1) + ((w2.z >> lane) & 1) + ((w3.z >> lane) & 1)
                        + ((w4.z >> lane) & 1) + ((w5.z >> lane) & 1) + ((w6.z >> lane) & 1) + ((w7.z >> lane) & 1);
                    c3 += ((w0.w >> lane) & 1) + ((w1.w >> lane) & 1) + ((w2.w >> lane) & 1) + ((w3.w >> lane) & 1)
                        + ((w4.w >> lane) & 1) + ((w5.w >> lane) & 1) + ((w6.w >> lane) & 1) + ((w7.w >> lane) & 1);
                }
                for (; e < end; e++) {
                    uint4 wv = __ldg(xb + __ldg(&d_colsrc[e]));
                    c0 += (wv.x >> lane) & 1;
                    c1 += (wv.y >> lane) & 1;
                    c2 += (wv.z >> lane) & 1;
                    c3 += (wv.w >> lane) & 1;
                }
            }
            Aimg[m * A_STRIDE + lane]      = (unsigned short)(__float_as_uint((float)c0) >> 16);
            Aimg[m * A_STRIDE + 32 + lane] = (unsigned short)(__float_as_uint((float)c1) >> 16);
            Aimg[m * A_STRIDE + 64 + lane] = (unsigned short)(__float_as_uint((float)c2) >> 16);
            Aimg[m * A_STRIDE + 96 + lane] = (unsigned short)(__float_as_uint((float)c3) >> 16);
        }

        // per-quad barrier: only warps 4*rg..4*rg+3 produce/consume these rows
        asm volatile("bar.sync %0, %1;" :: "r"(rg + 1), "r"(128) : "memory");

        // ---- warp GEMM accumulating onto acc (= deg*v carried in) ----
        const uint32_t aAddr0 = sbA + bufB + aOff0;
        const uint32_t aAddr1 = sbA + bufB + aOff1;
        #pragma unroll
        for (int ks = 0; ks < 8; ks++) {
            unsigned a0[4], a1[4];
            ldmatrix4(a0, aAddr0 + (uint32_t)(ks * 32));
            ldmatrix4(a1, aAddr1 + (uint32_t)(ks * 32));
            #pragma unroll
            for (int nt = 0; nt < 8; nt++) {
                int j = cg * 64 + nt * 8 + l4;
                uint4 B = __ldg(&d_W1q[(j * 8 + ks) * 4 + q]);
                mma_bf16(acc[0][nt], a0, B.x, B.y);
                mma_bf16(acc[1][nt], a1, B.x, B.y);
                mma_bf16(acc[0][nt], a0, B.z, B.w);
                mma_bf16(acc[1][nt], a1, B.z, B.w);
            }
        }

        // ---- LIF epilogue fully in registers ----
        #pragma unroll
        for (int rb = 0; rb < 2; rb++) {
            #pragma unroll
            for (int nt = 0; nt < 8; nt++) {
                #pragma unroll
                for (int h8 = 0; h8 < 2; h8++) {
                    const int r = rb * 2 + h8;
                    #pragma unroll
                    for (int p = 0; p < 2; p++) {
                        float vn = acc[rb][nt][h8 * 2 + p] * hidg[r];
                        const int slot = r * 16 + nt * 2 + p;
                        if (vn >= 0.25f) { Spk[slot >> 3] += 1u << ((slot & 7) * 4); vn = 0.f; }
                        acc[rb][nt][h8 * 2 + p] = vn * dcar[r];
                    }
                }
            }
        }
        // no CTA-wide sync: next iteration writes the OTHER buffer, and the
        // per-quad bar.sync above orders writes before the quad's own reads.
    }

    __syncthreads();

    // ---- fused readout: y = S @ M ----
    float* Msm  = (float*)dsm;
    float* yacc = (float*)(dsm + 10240);
    for (int i = tid; i < HID * N_OUT; i += 512) Msm[i] = d_M[i];
    for (int i = tid; i < TILE * N_OUT; i += 512) yacc[i] = 0.f;
    __syncthreads();

    #pragma unroll
    for (int r = 0; r < 4; r++) {
        float py[N_OUT];
        #pragma unroll
        for (int c = 0; c < N_OUT; c++) py[c] = 0.f;
        #pragma unroll
        for (int nt = 0; nt < 8; nt++) {
            #pragma unroll
            for (int p = 0; p < 2; p++) {
                const int slot = r * 16 + nt * 2 + p;
                float s = (float)((Spk[slot >> 3] >> ((slot & 7) * 4)) & 15u);
                const float* Mr = Msm + (cg * 64 + nt * 8 + q * 2 + p) * N_OUT;
                #pragma unroll
                for (int c = 0; c < N_OUT; c++) py[c] += s * Mr[c];
            }
        }
        #pragma unroll
        for (int c = 0; c < N_OUT; c++) {
            py[c] += __shfl_xor_sync(0xFFFFFFFFu, py[c], 1);
            py[c] += __shfl_xor_sync(0xFFFFFFFFu, py[c], 2);
        }
        if (q == 0) {
            int lr = rg * 32 + (r >> 1) * 16 + (r & 1) * 8 + l4;
            #pragma unroll
            for (int c = 0; c < N_OUT; c++)
                atomicAdd(&yacc[lr * N_OUT + c], py[c]);
        }
    }
    __syncthreads();

    for (int i = tid; i < TILE * N_OUT; i += 512) {
        int node = tile0 + i / N_OUT;
        if (node < N_NODES) d_y[(size_t)node * N_OUT + (i % N_OUT)] = yacc[i];
    }
}

// ---------------- pool + final ----------------
__global__ void pool_kernel(const int* __restrict__ batch) {
    int n = blockIdx.x * blockDim.x + threadIdx.x;
    if (n >= N_NODES) return;
    float acc[N_OUT];
    #pragma unroll
    for (int c = 0; c < N_OUT; c++) acc[c] = 0.f;
    int beg = d_rowptr[n], end = d_rowptr[n + 1];
    int e = beg;
    for (; e + 2 <= end; e += 2) {
        int s0 = __ldg(&d_colsrc[e]), s1 = __ldg(&d_colsrc[e + 1]);
        float w0 = __ldg(&d_invsqrt[s0]), w1 = __ldg(&d_invsqrt[s1]);
        const float* y0 = d_y + (size_t)s0 * N_OUT;
        const float* y1 = d_y + (size_t)s1 * N_OUT;
        #pragma unroll
        for (int c = 0; c < N_OUT; c++) acc[c] += w0 * __ldg(&y0[c]) + w1 * __ldg(&y1[c]);
    }
    for (; e < end; e++) {
        int s = __ldg(&d_colsrc[e]);
        float ws = __ldg(&d_invsqrt[s]);
        const float* yp = d_y + (size_t)s * N_OUT;
        #pragma unroll
        for (int c = 0; c < N_OUT; c++) acc[c] += ws * __ldg(&yp[c]);
    }
    float isn = d_invsqrt[n];
    const float* yn = d_y + (size_t)n * N_OUT;
    int g = batch[n];
    float sc = d_invcnt[g];
    #pragma unroll
    for (int c = 0; c < N_OUT; c++) {
        float z = acc[c] * isn + isn * isn * yn[c];
        atomicAdd(&d_P[g * N_OUT + c], z * sc);
    }
}

__global__ void final_kernel(const float* __restrict__ b2,
                             const float* __restrict__ Wlin,
                             const float* __restrict__ blin,
                             float* __restrict__ out) {
    int idx = blockIdx.x * blockDim.x + threadIdx.x;
    if (idx >= N_G * N_OUT) return;
    int c = idx % N_OUT;
    float b2w = 0.f;
    for (int k = 0; k < HID; k++) b2w += b2[k] * Wlin[k * N_OUT + c];
    out[idx] = d_P[idx] / 15.0f + b2w + blin[c];
}

// ---------------- launch ----------------
extern "C" void kernel_launch(void* const* d_in, const int* in_sizes, int n_in,
                              void* d_out, int out_size) {
    const float *x = 0, *W1 = 0, *W2 = 0, *b2 = 0, *Wlin = 0, *blin = 0;
    const int *src = 0, *dst = 0, *batch = 0;
    for (int i = 0; i < n_in; i++) {
        int s = in_sizes[i];
        void* p = d_in[i];
        if (s == N_NODES * F_IN)       x = (const float*)p;
        else if (s == F_IN * HID)      W1 = (const float*)p;
        else if (s == HID * HID)       W2 = (const float*)p;
        else if (s == HID)             b2 = (const float*)p;
        else if (s == HID * N_OUT)     Wlin = (const float*)p;
        else if (s == N_OUT)           blin = (const float*)p;
        else if (s == N_EDGES)         { if (!src) src = (const int*)p; else dst = (const int*)p; }
        else if (s == N_NODES)         batch = (const int*)p;
    }

    Keys keys;
    for (int t = 0; t < T_STEPS; t++) {
        uint32_t o0, o1;
        threefry_pair_host(0u, 42u, 0u, (uint32_t)t, &o0, &o1);
        keys.k0[t] = o0; keys.k1[t] = o1;
    }

    cudaFuncSetAttribute(fused_kernel, cudaFuncAttributeMaxDynamicSharedMemorySize, SMEM_DYN);

    init_kernel<<<(N_NODES + 255) / 256, 256>>>();
    mixA_kernel<<<RNG1_BLOCKS + CNT_BLOCKS, 256>>>(dst, batch, x, keys);
    scanP1<<<SCAN_NB, SCAN_TPB>>>();
    scanP2<<<1, 64>>>();
    scanP3<<<SCAN_NB, SCAN_TPB>>>();
    mixB_kernel<<<RNG2_BLOCKS + FILL_BLOCKS + PREP_BLOCKS + W1P_BLOCKS + 1, 256>>>(
        src, dst, x, W1, W2, Wlin, keys);
    fused_kernel<<<N_TILES, 512, SMEM_DYN>>>();
    pool_kernel<<<(N_NODES + 255) / 256, 256>>>(batch);
    final_kernel<<<(N_G * N_OUT + 255) / 256, 256>>>(b2, Wlin, blin, (float*)d_out);
}

// round 11
// speedup vs baseline: 1.1029x; 1.0036x over previous
#include <cuda_runtime.h>
#include <cuda_bf16.h>
#include <stdint.h>
#include <math.h>

#define N_NODES 50000
#define N_EDGES 800000
#define F_IN    128
#define HID     256
#define N_OUT   10
#define N_G     128
#define T_STEPS 15
#define TILE    128
#define N_TILES 391   // ceil(50000/128)

#define RNG_TOTAL   (T_STEPS * N_NODES * 4)          // 3,000,000
#define RNG1_BLOCKS 7000
#define RNG1_END    (RNG1_BLOCKS * 256)
#define RNG2_BLOCKS ((RNG_TOTAL - RNG1_END + 255) / 256)
#define CNT_BLOCKS  ((N_EDGES + 255) / 256)
#define FILL_BLOCKS ((N_EDGES + 255) / 256)
#define PREP_BLOCKS ((N_NODES + 255) / 256)
#define W1P_BLOCKS  32
#define SCAN_TPB    1024
#define SCAN_NB     ((N_NODES + SCAN_TPB - 1) / SCAN_TPB)

// ---------------- device scratch ----------------
__device__ uint4  d_xtbits4[(size_t)T_STEPS * N_NODES];  // 12 MB bitpacked x_t
__device__ uint4  d_W1q[8192];                           // 128KB packed bf16 hi/lo fragments
__device__ int    d_degcnt[N_NODES];
__device__ int    d_rowptr[N_NODES + 1];
__device__ int    d_cursor[N_NODES];
__device__ int    d_colsrc[N_EDGES];
__device__ int    d_bsum[SCAN_NB];
__device__ float  d_invdeg[N_NODES];
__device__ float  d_invsqrt[N_NODES];
__device__ int    d_gcnt[N_G];
__device__ float  d_invcnt[N_G];
__device__ float  d_M[HID * N_OUT];
__device__ float  d_y[(size_t)N_NODES * N_OUT];
__device__ float  d_P[N_G * N_OUT];

struct Keys { unsigned k0[T_STEPS]; unsigned k1[T_STEPS]; };

// ---------------- host threefry for subkeys ----------------
static void threefry_pair_host(uint32_t k0, uint32_t k1, uint32_t x0, uint32_t x1,
                               uint32_t* o0, uint32_t* o1) {
    uint32_t ks2 = k0 ^ k1 ^ 0x1BD11BDAu;
    x0 += k0; x1 += k1;
#define HR(R) { x0 += x1; x1 = (x1 << R) | (x1 >> (32 - R)); x1 ^= x0; }
    HR(13) HR(15) HR(26) HR(6)
    x0 += k1; x1 += ks2 + 1u;
    HR(17) HR(29) HR(16) HR(24)
    x0 += ks2; x1 += k0 + 2u;
    HR(13) HR(15) HR(26) HR(6)
    x0 += k0; x1 += k1 + 3u;
    HR(17) HR(29) HR(16) HR(24)
    x0 += k1; x1 += ks2 + 4u;
    HR(13) HR(15) HR(26) HR(6)
    x0 += ks2; x1 += k0 + 5u;
#undef HR
    *o0 = x0; *o1 = x1;
}

// ---------------- device RNG body ----------------
#define DR(R) { x0 += x1; x1 = __funnelshift_l(x1, x1, R); x1 ^= x0; }

__device__ __forceinline__ void rng_body(int gid, const float* __restrict__ x, const Keys& keys) {
    if (gid >= RNG_TOTAL) return;
    int w  = gid & 3;
    int nw = gid >> 2;
    int n  = nw % N_NODES;
    int t  = nw / N_NODES;
    const unsigned k0 = keys.k0[t];
    const unsigned k1 = keys.k1[t];
    const unsigned ks2 = k0 ^ k1 ^ 0x1BD11BDAu;
    const unsigned base = (unsigned)(n * F_IN + w * 32);
    const float* xr = x + n * F_IN + w * 32;
    unsigned outw = 0u;
    #pragma unroll 4
    for (int b = 0; b < 32; b++) {
        unsigned x0 = k0;
        unsigned x1 = base + (unsigned)b + k1;
        DR(13) DR(15) DR(26) DR(6)
        x0 += k1;  x1 += ks2 + 1u;
        DR(17) DR(29) DR(16) DR(24)
        x0 += ks2; x1 += k0 + 2u;
        DR(13) DR(15) DR(26) DR(6)
        x0 += k0;  x1 += k1 + 3u;
        DR(17) DR(29) DR(16) DR(24)
        x0 += k1;  x1 += ks2 + 4u;
        DR(13) DR(15) DR(26) DR(6)
        x0 += ks2; x1 += k0 + 5u;
        unsigned bits = x0 ^ x1;
        float u = __uint_as_float((bits >> 9) | 0x3f800000u) - 1.0f;
        if (u < xr[b]) outw |= (1u << b);
    }
    ((unsigned*)d_xtbits4)[gid] = outw;
}
#undef DR

// ---------------- prep bodies ----------------
__global__ void init_kernel() {
    int i = blockIdx.x * blockDim.x + threadIdx.x;
    if (i < N_NODES) { d_degcnt[i] = 0; d_cursor[i] = 0; }
    if (i < N_G)     d_gcnt[i] = 0;
    if (i < N_G * N_OUT) d_P[i] = 0.f;
}

__device__ __forceinline__ unsigned short f2bf_hi(float w) {
    return (unsigned short)__bfloat16_as_ushort(__float2bfloat16(w));
}

__device__ __forceinline__ void w1pack_body(int idx, const float* __restrict__ W1) {
    if (idx >= 8192) return;
    int q = idx & 3, ks = (idx >> 2) & 7, j = idx >> 5;
    int k0 = ks * 16;
    int ka = k0 + 2 * q;
    int kb = k0 + 8 + 2 * q;
    float wa0 = W1[ka * HID + j],       wa1 = W1[(ka + 1) * HID + j];
    float wb0 = W1[kb * HID + j],       wb1 = W1[(kb + 1) * HID + j];
    unsigned short ha0 = f2bf_hi(wa0), ha1 = f2bf_hi(wa1);
    unsigned short hb0 = f2bf_hi(wb0), hb1 = f2bf_hi(wb1);
    float ra0 = wa0 - __bfloat162float(__ushort_as_bfloat16(ha0));
    float ra1 = wa1 - __bfloat162float(__ushort_as_bfloat16(ha1));
    float rb0 = wb0 - __bfloat162float(__ushort_as_bfloat16(hb0));
    float rb1 = wb1 - __bfloat162float(__ushort_as_bfloat16(hb1));
    uint4 o;
    o.x = (unsigned)ha0 | ((unsigned)ha1 << 16);
    o.y = (unsigned)hb0 | ((unsigned)hb1 << 16);
    o.z = (unsigned)f2bf_hi(ra0) | ((unsigned)f2bf_hi(ra1) << 16);
    o.w = (unsigned)f2bf_hi(rb0) | ((unsigned)f2bf_hi(rb1) << 16);
    d_W1q[idx] = o;
}

__device__ __forceinline__ void mk_body(int h, const float* __restrict__ W2,
                                        const float* __restrict__ Wlin) {
    float acc[N_OUT];
    #pragma unroll
    for (int c = 0; c < N_OUT; c++) acc[c] = 0.f;
    for (int k = 0; k < HID; k++) {
        float w = W2[h * HID + k];
        #pragma unroll
        for (int c = 0; c < N_OUT; c++) acc[c] += w * Wlin[k * N_OUT + c];
    }
    #pragma unroll
    for (int c = 0; c < N_OUT; c++) d_M[h * N_OUT + c] = acc[c];
}

// ---------------- mixA: counts || RNG part 1 ----------------
__global__ __launch_bounds__(256) void mixA_kernel(const int* __restrict__ dst,
                                                   const int* __restrict__ batch,
                                                   const float* __restrict__ x, Keys keys) {
    int bid = blockIdx.x, tid = threadIdx.x;
    if (bid < RNG1_BLOCKS) {
        rng_body(bid * 256 + tid, x, keys);
    } else {
        int e = (bid - RNG1_BLOCKS) * 256 + tid;
        if (e < N_EDGES) atomicAdd(&d_degcnt[dst[e]], 1);
        if (e < N_NODES) atomicAdd(&d_gcnt[batch[e]], 1);
    }
}

// ---------------- 3-phase scan ----------------
__global__ void scanP1() {
    __shared__ int wsum[32];
    int b = blockIdx.x, tid = threadIdx.x, lane = tid & 31, w = tid >> 5;
    int i = b * SCAN_TPB + tid;
    int v = (i < N_NODES) ? d_degcnt[i] : 0;
    int s = v;
    #pragma unroll
    for (int off = 16; off > 0; off >>= 1) s += __shfl_down_sync(0xFFFFFFFFu, s, off);
    if (lane == 0) wsum[w] = s;
    __syncthreads();
    if (w == 0) {
        int t = (lane < SCAN_TPB / 32) ? wsum[lane] : 0;
        #pragma unroll
        for (int off = 16; off > 0; off >>= 1) t += __shfl_down_sync(0xFFFFFFFFu, t, off);
        if (lane == 0) d_bsum[b] = t;
    }
}

__global__ void scanP2() {
    __shared__ int sh[64];
    int tid = threadIdx.x;   // 64 threads
    sh[tid] = (tid < SCAN_NB) ? d_bsum[tid] : 0;
    __syncthreads();
    for (int off = 1; off < 64; off <<= 1) {
        int t = (tid >= off) ? sh[tid - off] : 0;
        __syncthreads();
        sh[tid] += t;
        __syncthreads();
    }
    if (tid < SCAN_NB) {
        int incl = sh[tid];
        int own = (tid == 0) ? incl : incl - sh[tid - 1];
        d_bsum[tid] = incl - own;
    }
    if (tid == 63) d_rowptr[N_NODES] = sh[SCAN_NB - 1];
}

__global__ void scanP3() {
    __shared__ int wsum[32];
    int b = blockIdx.x, tid = threadIdx.x, lane = tid & 31, w = tid >> 5;
    int i = b * SCAN_TPB + tid;
    int v = (i < N_NODES) ? d_degcnt[i] : 0;
    int xs = v;
    #pragma unroll
    for (int off = 1; off < 32; off <<= 1) {
        int y = __shfl_up_sync(0xFFFFFFFFu, xs, off);
        if (lane >= off) xs += y;
    }
    if (lane == 31) wsum[w] = xs;
    __syncthreads();
    if (w == 0) {
        int s = wsum[lane];
        #pragma unroll
        for (int off = 1; off < 32; off <<= 1) {
            int y = __shfl_up_sync(0xFFFFFFFFu, s, off);
            if (lane >= off) s += y;
        }
        wsum[lane] = s;
    }
    __syncthreads();
    int pre = (w > 0 ? wsum[w - 1] : 0) + (xs - v) + d_bsum[b];
    if (i < N_NODES) d_rowptr[i] = pre;
}

// ---------------- mixB: csr_fill || preps || w1pack || mk || RNG part 2 ----------------
__global__ __launch_bounds__(256) void mixB_kernel(const int* __restrict__ src,
                                                   const int* __restrict__ dst,
                                                   const float* __restrict__ x,
                                                   const float* __restrict__ W1,
                                                   const float* __restrict__ W2,
                                                   const float* __restrict__ Wlin,
                                                   Keys keys) {
    int bid = blockIdx.x, tid = threadIdx.x;
    if (bid < RNG2_BLOCKS) {
        rng_body(RNG1_END + bid * 256 + tid, x, keys);
        return;
    }
    bid -= RNG2_BLOCKS;
    if (bid < FILL_BLOCKS) {
        int e = bid * 256 + tid;
        if (e < N_EDGES) {
            int d = dst[e];
            int p = atomicAdd(&d_cursor[d], 1);
            d_colsrc[d_rowptr[d] + p] = src[e];
        }
        return;
    }
    bid -= FILL_BLOCKS;
    if (bid < PREP_BLOCKS) {
        int n = bid * 256 + tid;
        if (n < N_NODES) {
            int c = d_degcnt[n];
            int cm = c > 1 ? c : 1;
            d_invdeg[n] = 1.0f / (float)cm;
            d_invsqrt[n] = 1.0f / sqrtf((float)(c + 1));
        }
        if (n < N_G) {
            int c = d_gcnt[n];
            d_invcnt[n] = 1.0f / (float)(c > 1 ? c : 1);
        }
        return;
    }
    bid -= PREP_BLOCKS;
    if (bid < W1P_BLOCKS) {
        w1pack_body(bid * 256 + tid, W1);
        return;
    }
    bid -= W1P_BLOCKS;
    if (bid == 0) mk_body(tid, W2, Wlin);
}

// ---------------- warp-mma helpers ----------------
__device__ __forceinline__ void mma_bf16(float* d, const unsigned* a, unsigned b0, unsigned b1) {
    asm volatile(
        "mma.sync.aligned.m16n8k16.row.col.f32.bf16.bf16.f32 "
        "{%0,%1,%2,%3}, {%4,%5,%6,%7}, {%8,%9}, {%0,%1,%2,%3};"
        : "+f"(d[0]), "+f"(d[1]), "+f"(d[2]), "+f"(d[3])
        : "r"(a[0]), "r"(a[1]), "r"(a[2]), "r"(a[3]), "r"(b0), "r"(b1));
}

__device__ __forceinline__ void ldmatrix4(unsigned* r, uint32_t addr) {
    asm volatile("ldmatrix.sync.aligned.m8n8.x4.shared.b16 {%0,%1,%2,%3}, [%4];"
        : "=r"(r[0]), "=r"(r[1]), "=r"(r[2]), "=r"(r[3]) : "r"(addr));
}

// ---------------- fused time-loop megakernel ----------------
// dynamic smem: A double buffer, 2 x (128 x 136 bf16) = 2 x 34816 B = 69632 B.
// Quad q (warps 4q..4q+3) writes A rows [32q,32q+32) and is the ONLY reader of
// those rows (ldmatrix) -> per-quad named barrier replaces CTA-wide syncthreads.
// After the t-loop the buffer is reused for readout (M + yacc).
#define A_STRIDE 136
#define A_BUF_BYTES (TILE * A_STRIDE * 2)
#define SMEM_DYN (2 * A_BUF_BYTES)

extern __shared__ char dsm[];

__global__ __launch_bounds__(512) void fused_kernel() {
    const int tid = threadIdx.x;
    const int wid = tid >> 5, lane = tid & 31;
    const int tile0 = blockIdx.x * TILE;
    const int rg = wid >> 2, cg = wid & 3;   // quad = rg
    const int q = lane & 3, l4 = lane >> 2;

    uint32_t sbA;
    asm("{ .reg .u64 t; cvta.to.shared.u64 t, %1; cvt.u32.u64 %0, t; }" : "=r"(sbA) : "l"(dsm));

    // carry: v' = (count + deg*v) * (0.5*invdeg) == 0.5*h + 0.5*v
    float hidg[4], dcar[4];
    #pragma unroll
    for (int r = 0; r < 4; r++) {
        int lr = rg * 32 + (r >> 1) * 16 + (r & 1) * 8 + l4;
        int n = tile0 + lr;
        if (n < N_NODES) {
            int c = d_degcnt[n];
            int cm = c > 1 ? c : 1;
            hidg[r] = 0.5f * d_invdeg[n];
            dcar[r] = (float)cm;
        } else { hidg[r] = 0.f; dcar[r] = 0.f; }
    }

    unsigned Spk[8];
    #pragma unroll
    for (int i = 0; i < 8; i++) Spk[i] = 0u;

    float acc[2][8][4];
    #pragma unroll
    for (int rb = 0; rb < 2; rb++)
        #pragma unroll
        for (int nt = 0; nt < 8; nt++)
            #pragma unroll
            for (int k = 0; k < 4; k++) acc[rb][nt][k] = 0.f;

    const uint32_t aOff0 = (uint32_t)(((rg * 32 + (lane & 15)) * A_STRIDE + (lane >> 4) * 8) * 2);
    const uint32_t aOff1 = aOff0 + 16 * A_STRIDE * 2;

    for (int t = 0; t < T_STEPS; t++) {
        const uint32_t bufB = (uint32_t)((t & 1) * A_BUF_BYTES);
        unsigned short* Aimg = (unsigned short*)(dsm + bufB);

        // ---- aggregation: warp wid fills its 8 rows, MLP=8 ----
        const uint4* xb = d_xtbits4 + (size_t)t * N_NODES;
        #pragma unroll 1
        for (int i = 0; i < 8; i++) {
            int m = wid * 8 + i;
            int n = tile0 + m;
            int c0 = 0, c1 = 0, c2 = 0, c3 = 0;
            if (n < N_NODES) {
                int beg = __ldg(&d_rowptr[n]), end = __ldg(&d_rowptr[n + 1]);
                int e = beg;
                #pragma unroll 1
                for (; e + 8 <= end; e += 8) {
                    int s0 = __ldg(&d_colsrc[e]),     s1 = __ldg(&d_colsrc[e + 1]);
                    int s2 = __ldg(&d_colsrc[e + 2]), s3 = __ldg(&d_colsrc[e + 3]);
                    int s4 = __ldg(&d_colsrc[e + 4]), s5 = __ldg(&d_colsrc[e + 5]);
                    int s6 = __ldg(&d_colsrc[e + 6]), s7 = __ldg(&d_colsrc[e + 7]);
                    uint4 w0 = __ldg(xb + s0), w1 = __ldg(xb + s1);
                    uint4 w2 = __ldg(xb + s2), w3 = __ldg(xb + s3);
                    uint4 w4 = __ldg(xb + s4), w5 = __ldg(xb + s5);
                    uint4 w6 = __ldg(xb + s6), w7 = __ldg(xb + s7);
                    c0 += ((w0.x >> lane) & 1) + ((w1.x >> lane) & 1) + ((w2.x >> lane) & 1) + ((w3.x >> lane) & 1)
                        + ((w4.x >> lane) & 1) + ((w5.x >> lane) & 1) + ((w6.x >> lane) & 1) + ((w7.x >> lane) & 1);
                    c1 += ((w0.y >> lane) & 1) + ((w1.y >> lane) & 1) + ((w2.y >> lane) & 1) + ((w3.y >> lane) & 1)
                        + ((w4.y >> lane) & 1) + ((w5.y >> lane) & 1) + ((w6.y >> lane) & 1) + ((w7.y >> lane) & 1);
                    c2 += ((w0.z >> lane) & 1) + ((w1.z >> lane) & 1) + ((w2.z >> lane) & 1) + ((w3.z >> lane) & 1)
                        + ((w4.z >> lane) & 1) + ((w5.z >> lane) & 1) + ((w6.z >> lane) & 1) + ((w7.z >> lane) & 1);
                    c3 += ((w0.w >> lane) & 1) + ((w1.w >> lane) & 1) + ((w2.w >> lane) & 1) + ((w3.w >> lane) & 1)
                        + ((w4.w >> lane) & 1) + ((w5.w >> lane) & 1) + ((w6.w >> lane) & 1) + ((w7.w >> lane) & 1);
                }
                for (; e < end; e++) {
                    uint4 wv = __ldg(xb + __ldg(&d_colsrc[e]));
                    c0 += (wv.x >> lane) & 1;
                    c1 += (wv.y >> lane) & 1;
                    c2 += (wv.z >> lane) & 1;
                    c3 += (wv.w >> lane) & 1;
                }
            }
            Aimg[m * A_STRIDE + lane]      = (unsigned short)(__float_as_uint((float)c0) >> 16);
            Aimg[m * A_STRIDE + 32 + lane] = (unsigned short)(__float_as_uint((float)c1) >> 16);
            Aimg[m * A_STRIDE + 64 + lane] = (unsigned short)(__float_as_uint((float)c2) >> 16);
            Aimg[m * A_STRIDE + 96 + lane] = (unsigned short)(__float_as_uint((float)c3) >> 16);
        }

        // per-quad barrier: only warps 4*rg..4*rg+3 produce/consume these rows
        asm volatile("bar.sync %0, %1;" :: "r"(rg + 1), "r"(128) : "memory");

        // ---- warp GEMM accumulating onto acc (= deg*v carried in) ----
        const uint32_t aAddr0 = sbA + bufB + aOff0;
        const uint32_t aAddr1 = sbA + bufB + aOff1;
        #pragma unroll
        for (int ks = 0; ks < 8; ks++) {
            unsigned a0[4], a1[4];
            ldmatrix4(a0, aAddr0 + (uint32_t)(ks * 32));
            ldmatrix4(a1, aAddr1 + (uint32_t)(ks * 32));
            #pragma unroll
            for (int nt = 0; nt < 8; nt++) {
                int j = cg * 64 + nt * 8 + l4;
                uint4 B = __ldg(&d_W1q[(j * 8 + ks) * 4 + q]);
                mma_bf16(acc[0][nt], a0, B.x, B.y);
                mma_bf16(acc[1][nt], a1, B.x, B.y);
                mma_bf16(acc[0][nt], a0, B.z, B.w);
                mma_bf16(acc[1][nt], a1, B.z, B.w);
            }
        }

        // ---- LIF epilogue fully in registers ----
        #pragma unroll
        for (int rb = 0; rb < 2; rb++) {
            #pragma unroll
            for (int nt = 0; nt < 8; nt++) {
                #pragma unroll
                for (int h8 = 0; h8 < 2; h8++) {
                    const int r = rb * 2 + h8;
                    #pragma unroll
                    for (int p = 0; p < 2; p++) {
                        float vn = acc[rb][nt][h8 * 2 + p] * hidg[r];
                        const int slot = r * 16 + nt * 2 + p;
                        if (vn >= 0.25f) { Spk[slot >> 3] += 1u << ((slot & 7) * 4); vn = 0.f; }
                        acc[rb][nt][h8 * 2 + p] = vn * dcar[r];
                    }
                }
            }
        }
        // no CTA-wide sync: next iteration writes the OTHER buffer, and the
        // per-quad bar.sync above orders writes before the quad's own reads.
    }

    __syncthreads();

    // ---- fused readout: y = S @ M ----
    float* Msm  = (float*)dsm;
    float* yacc = (float*)(dsm + 10240);
    for (int i = tid; i < HID * N_OUT; i += 512) Msm[i] = d_M[i];
    for (int i = tid; i < TILE * N_OUT; i += 512) yacc[i] = 0.f;
    __syncthreads();

    #pragma unroll
    for (int r = 0; r < 4; r++) {
        float py[N_OUT];
        #pragma unroll
        for (int c = 0; c < N_OUT; c++) py[c] = 0.f;
        #pragma unroll
        for (int nt = 0; nt < 8; nt++) {
            #pragma unroll
            for (int p = 0; p < 2; p++) {
                const int slot = r * 16 + nt * 2 + p;
                float s = (float)((Spk[slot >> 3] >> ((slot & 7) * 4)) & 15u);
                const float* Mr = Msm + (cg * 64 + nt * 8 + q * 2 + p) * N_OUT;
                #pragma unroll
                for (int c = 0; c < N_OUT; c++) py[c] += s * Mr[c];
            }
        }
        #pragma unroll
        for (int c = 0; c < N_OUT; c++) {
            py[c] += __shfl_xor_sync(0xFFFFFFFFu, py[c], 1);
            py[c] += __shfl_xor_sync(0xFFFFFFFFu, py[c], 2);
        }
        if (q == 0) {
            int lr = rg * 32 + (r >> 1) * 16 + (r & 1) * 8 + l4;
            #pragma unroll
            for (int c = 0; c < N_OUT; c++)
                atomicAdd(&yacc[lr * N_OUT + c], py[c]);
        }
    }
    __syncthreads();

    for (int i = tid; i < TILE * N_OUT; i += 512) {
        int node = tile0 + i / N_OUT;
        if (node < N_NODES) d_y[(size_t)node * N_OUT + (i % N_OUT)] = yacc[i];
    }
}

// ---------------- pool + final ----------------
__global__ void pool_kernel(const int* __restrict__ batch) {
    int n = blockIdx.x * blockDim.x + threadIdx.x;
    if (n >= N_NODES) return;
    float acc[N_OUT];
    #pragma unroll
    for (int c = 0; c < N_OUT; c++) acc[c] = 0.f;
    int beg = d_rowptr[n], end = d_rowptr[n + 1];
    int e = beg;
    for (; e + 2 <= end; e += 2) {
        int s0 = __ldg(&d_colsrc[e]), s1 = __ldg(&d_colsrc[e + 1]);
        float w0 = __ldg(&d_invsqrt[s0]), w1 = __ldg(&d_invsqrt[s1]);
        const float* y0 = d_y + (size_t)s0 * N_OUT;
        const float* y1 = d_y + (size_t)s1 * N_OUT;
        #pragma unroll
        for (int c = 0; c < N_OUT; c++) acc[c] += w0 * __ldg(&y0[c]) + w1 * __ldg(&y1[c]);
    }
    for (; e < end; e++) {
        int s = __ldg(&d_colsrc[e]);
        float ws = __ldg(&d_invsqrt[s]);
        const float* yp = d_y + (size_t)s * N_OUT;
        #pragma unroll
        for (int c = 0; c < N_OUT; c++) acc[c] += ws * __ldg(&yp[c]);
    }
    float isn = d_invsqrt[n];
    const float* yn = d_y + (size_t)n * N_OUT;
    int g = batch[n];
    float sc = d_invcnt[g];
    #pragma unroll
    for (int c = 0; c < N_OUT; c++) {
        float z = acc[c] * isn + isn * isn * yn[c];
        atomicAdd(&d_P[g * N_OUT + c], z * sc);
    }
}

__global__ void final_kernel(const float* __restrict__ b2,
                             const float* __restrict__ Wlin,
                             const float* __restrict__ blin,
                             float* __restrict__ out) {
    int idx = blockIdx.x * blockDim.x + threadIdx.x;
    if (idx >= N_G * N_OUT) return;
    int c = idx % N_OUT;
    float b2w = 0.f;
    for (int k = 0; k < HID; k++) b2w += b2[k] * Wlin[k * N_OUT + c];
    out[idx] = d_P[idx] / 15.0f + b2w + blin[c];
}

// ---------------- launch ----------------
extern "C" void kernel_launch(void* const* d_in, const int* in_sizes, int n_in,
                              void* d_out, int out_size) {
    const float *x = 0, *W1 = 0, *W2 = 0, *b2 = 0, *Wlin = 0, *blin = 0;
    const int *src = 0, *dst = 0, *batch = 0;
    for (int i = 0; i < n_in; i++) {
        int s = in_sizes[i];
        void* p = d_in[i];
        if (s == N_NODES * F_IN)       x = (const float*)p;
        else if (s == F_IN * HID)      W1 = (const float*)p;
        else if (s == HID * HID)       W2 = (const float*)p;
        else if (s == HID)             b2 = (const float*)p;
        else if (s == HID * N_OUT)     Wlin = (const float*)p;
        else if (s == N_OUT)           blin = (const float*)p;
        else if (s == N_EDGES)         { if (!src) src = (const int*)p; else dst = (const int*)p; }
        else if (s == N_NODES)         batch = (const int*)p;
    }

    Keys keys;
    for (int t = 0; t < T_STEPS; t++) {
        uint32_t o0, o1;
        threefry_pair_host(0u, 42u, 0u, (uint32_t)t, &o0, &o1);
        keys.k0[t] = o0; keys.k1[t] = o1;
    }

    cudaFuncSetAttribute(fused_kernel, cudaFuncAttributeMaxDynamicSharedMemorySize, SMEM_DYN);

    init_kernel<<<(N_NODES + 255) / 256, 256>>>();
    mixA_kernel<<<RNG1_BLOCKS + CNT_BLOCKS, 256>>>(dst, batch, x, keys);
    scanP1<<<SCAN_NB, SCAN_TPB>>>();
    scanP2<<<1, 64>>>();
    scanP3<<<SCAN_NB, SCAN_TPB>>>();
    mixB_kernel<<<RNG2_BLOCKS + FILL_BLOCKS + PREP_BLOCKS + W1P_BLOCKS + 1, 256>>>(
        src, dst, x, W1, W2, Wlin, keys);
    fused_kernel<<<N_TILES, 512, SMEM_DYN>>>();
    pool_kernel<<<(N_NODES + 255) / 256, 256>>>(batch);
    final_kernel<<<(N_G * N_OUT + 255) / 256, 256>>>(b2, Wlin, blin, (float*)d_out);
}